// round 6
// baseline (speedup 1.0000x reference)
#include <cuda_runtime.h>
#include <cuda_bf16.h>
#include <cstdint>

#define NROWS   131072
#define NTILES  1024
#define O_XN2   8388608
#define O_PROTO 16777216
#define O_CVAE  83886080
#define O_PROT  83886081
#define GRID    152
#define INF_F   __int_as_float(0x7f800000)

// device scratch (allowed: static __device__ arrays)
__device__ __nv_bfloat16 g_Whi[512 * 64];
__device__ __nv_bfloat16 g_Wlo[512 * 64];
__device__ float    g_b2[512];
__device__ unsigned g_colmin[512];
__device__ float    g_partial[GRID];

// smem word layout (u32/f32 units)
#define W_WHI 0
#define W_WLO (512*36)
#define W_B2  (2*512*36)
#define W_CM  (W_B2 + 512)
#define W_XS  (W_CM + 512)          // 8 warps * 16 rows * 66 floats
#define W_A2  (W_XS + 8*16*66)
#define W_WS  (W_A2 + 128)
#define SMEM_BYTES ((W_WS + 8) * 4)

__device__ __forceinline__ void mma16816(float* c, const uint32_t* a, uint32_t b0, uint32_t b1) {
    asm volatile(
        "mma.sync.aligned.m16n8k16.row.col.f32.bf16.bf16.f32 "
        "{%0,%1,%2,%3}, {%4,%5,%6,%7}, {%8,%9}, {%0,%1,%2,%3};"
        : "+f"(c[0]), "+f"(c[1]), "+f"(c[2]), "+f"(c[3])
        : "r"(a[0]), "r"(a[1]), "r"(a[2]), "r"(a[3]), "r"(b0), "r"(b1));
}

__device__ __forceinline__ void split2(float x, float y, uint32_t& hi, uint32_t& lo) {
    unsigned short hx = __bfloat16_as_ushort(__float2bfloat16(x));
    unsigned short hy = __bfloat16_as_ushort(__float2bfloat16(y));
    float rx = x - __bfloat162float(__ushort_as_bfloat16(hx));
    float ry = y - __bfloat162float(__ushort_as_bfloat16(hy));
    unsigned short lx = __bfloat16_as_ushort(__float2bfloat16(rx));
    unsigned short ly = __bfloat16_as_ushort(__float2bfloat16(ry));
    hi = (uint32_t)hx | ((uint32_t)hy << 16);
    lo = (uint32_t)lx | ((uint32_t)ly << 16);
}

// ---------------- prep ----------------
__global__ void swav_prep(const float* __restrict__ W, const float* __restrict__ rec,
                          const float* __restrict__ kl, const float* __restrict__ mmd,
                          float* __restrict__ out) {
    int k = blockIdx.x, lane = threadIdx.x;      // 512 x 32
    float w0 = W[k * 64 + lane], w1 = W[k * 64 + 32 + lane];
    uint32_t hi, lo;
    split2(w0, w1, hi, lo);
    g_Whi[k * 64 + lane]      = __ushort_as_bfloat16((unsigned short)(hi & 0xffff));
    g_Whi[k * 64 + 32 + lane] = __ushort_as_bfloat16((unsigned short)(hi >> 16));
    g_Wlo[k * 64 + lane]      = __ushort_as_bfloat16((unsigned short)(lo & 0xffff));
    g_Wlo[k * 64 + 32 + lane] = __ushort_as_bfloat16((unsigned short)(lo >> 16));
    float s = w0 * w0 + w1 * w1;
    #pragma unroll
    for (int m = 16; m; m >>= 1) s += __shfl_xor_sync(0xffffffffu, s, m);
    if (lane == 0) { g_b2[k] = s; g_colmin[k] = 0x7f800000u; }
    if (k == 0 && lane == 0) out[O_CVAE] = rec[0] + 0.5f * kl[0] + mmd[0];
}

// ---------------- main ----------------
__global__ void __launch_bounds__(256, 1)
swav_main(const float* __restrict__ x, float* __restrict__ out) {
    extern __shared__ uint32_t sm[];
    int tid = threadIdx.x, wid = tid >> 5, lane = tid & 31;
    int g = lane >> 2, t = lane & 3;

    const uint32_t* gwh = (const uint32_t*)g_Whi;
    const uint32_t* gwl = (const uint32_t*)g_Wlo;
    for (int i = tid; i < 512 * 32; i += 256) {
        int k = i >> 5, c = i & 31;
        sm[W_WHI + k * 36 + c] = gwh[i];
        sm[W_WLO + k * 36 + c] = gwl[i];
    }
    float* s_b2 = (float*)(sm + W_B2);
    unsigned* s_cm = sm + W_CM;
    for (int i = tid; i < 512; i += 256) { s_b2[i] = g_b2[i]; s_cm[i] = 0x7f800000u; }
    __syncthreads();

    float* xs = (float*)(sm + W_XS) + wid * (16 * 66);
    float* s_a2 = (float*)(sm + W_A2);
    float rowacc = 0.f;

    for (int tile = blockIdx.x; tile < NTILES; tile += GRID) {
        int rbase = tile * 128 + wid * 16;
        // normalize 16 rows, write xn twice, stage in smem
        #pragma unroll
        for (int r = 0; r < 16; r++) {
            int row = rbase + r;
            float2 v = ((const float2*)x)[row * 32 + lane];
            float s = v.x * v.x + v.y * v.y;
            #pragma unroll
            for (int m = 16; m; m >>= 1) s += __shfl_xor_sync(0xffffffffu, s, m);
            float inv = 1.0f / fmaxf(sqrtf(s), 1e-12f);
            float2 xnv = make_float2(v.x * inv, v.y * inv);
            ((float2*)out)[row * 32 + lane] = xnv;
            ((float2*)(out + O_XN2))[row * 32 + lane] = xnv;
            ((float2*)(xs + r * 66))[lane] = xnv;
            if (lane == 0) s_a2[wid * 16 + r] = s * inv * inv;
        }
        __syncwarp();
        float a2g = s_a2[wid * 16 + g], a2g8 = s_a2[wid * 16 + g + 8];

        // A fragments (hi/lo), 4 k-steps
        uint32_t Ah[4][4], Al[4][4];
        #pragma unroll
        for (int ks = 0; ks < 4; ks++) {
            const float* rg = xs + g * 66 + ks * 16 + 2 * t;
            const float* rh = xs + (g + 8) * 66 + ks * 16 + 2 * t;
            split2(rg[0], rg[1], Ah[ks][0], Al[ks][0]);
            split2(rh[0], rh[1], Ah[ks][1], Al[ks][1]);
            split2(rg[8], rg[9], Ah[ks][2], Al[ks][2]);
            split2(rh[8], rh[9], Ah[ks][3], Al[ks][3]);
        }

        float rmA = INF_F, rmB = INF_F;
        for (int nc = 0; nc < 8; nc++) {
            float C[8][4];
            #pragma unroll
            for (int nt = 0; nt < 8; nt++)
                C[nt][0] = C[nt][1] = C[nt][2] = C[nt][3] = 0.f;

            #pragma unroll
            for (int ks = 0; ks < 4; ks++) {
                uint32_t bh[8][2], bl[8][2];
                #pragma unroll
                for (int nt = 0; nt < 8; nt++) {
                    int col = nc * 64 + nt * 8 + g;
                    const uint32_t* ph = sm + W_WHI + col * 36 + ks * 8 + t;
                    const uint32_t* pl = sm + W_WLO + col * 36 + ks * 8 + t;
                    bh[nt][0] = ph[0]; bh[nt][1] = ph[4];
                    bl[nt][0] = pl[0]; bl[nt][1] = pl[4];
                }
                #pragma unroll
                for (int nt = 0; nt < 8; nt++) {
                    mma16816(C[nt], Ah[ks], bh[nt][0], bh[nt][1]);
                    mma16816(C[nt], Al[ks], bh[nt][0], bh[nt][1]);
                    mma16816(C[nt], Ah[ks], bl[nt][0], bl[nt][1]);
                }
            }
            // epilogue for this 64-col chunk
            #pragma unroll
            for (int nt = 0; nt < 8; nt++) {
                int col0 = nc * 64 + nt * 8 + 2 * t;
                int rg_ = rbase + g, rh_ = rbase + g + 8;
                ((float2*)(out + O_PROTO))[(rg_ * 512 + col0) >> 1] = make_float2(C[nt][0], C[nt][1]);
                ((float2*)(out + O_PROTO))[(rh_ * 512 + col0) >> 1] = make_float2(C[nt][2], C[nt][3]);
                float b2a = s_b2[col0], b2b = s_b2[col0 + 1];
                float u00 = fmaxf(fmaf(-2.f, C[nt][0], a2g + b2a), 1e-12f);
                float u01 = fmaxf(fmaf(-2.f, C[nt][1], a2g + b2b), 1e-12f);
                float u10 = fmaxf(fmaf(-2.f, C[nt][2], a2g8 + b2a), 1e-12f);
                float u11 = fmaxf(fmaf(-2.f, C[nt][3], a2g8 + b2b), 1e-12f);
                rmA = fminf(rmA, fminf(u00, u01));
                rmB = fminf(rmB, fminf(u10, u11));
                float m0 = fminf(u00, u10), m1 = fminf(u01, u11);
                #pragma unroll
                for (int m = 4; m <= 16; m <<= 1) {
                    m0 = fminf(m0, __shfl_xor_sync(0xffffffffu, m0, m));
                    m1 = fminf(m1, __shfl_xor_sync(0xffffffffu, m1, m));
                }
                if (g == 0) {
                    atomicMin(&s_cm[col0], __float_as_uint(m0));
                    atomicMin(&s_cm[col0 + 1], __float_as_uint(m1));
                }
            }
        }
        // row-min: reduce over t lanes, then sqrt + warp-sum
        rmA = fminf(rmA, __shfl_xor_sync(0xffffffffu, rmA, 1));
        rmA = fminf(rmA, __shfl_xor_sync(0xffffffffu, rmA, 2));
        rmB = fminf(rmB, __shfl_xor_sync(0xffffffffu, rmB, 1));
        rmB = fminf(rmB, __shfl_xor_sync(0xffffffffu, rmB, 2));
        float val = (t == 0) ? (sqrtf(rmA) + sqrtf(rmB)) : 0.f;
        #pragma unroll
        for (int m = 1; m <= 16; m <<= 1) val += __shfl_xor_sync(0xffffffffu, val, m);
        rowacc += val;
    }

    float* s_ws = (float*)(sm + W_WS);
    if (lane == 0) s_ws[wid] = rowacc;
    __syncthreads();
    if (tid == 0) {
        float s = 0.f;
        for (int i = 0; i < 8; i++) s += s_ws[i];
        g_partial[blockIdx.x] = s;
    }
    for (int c = tid; c < 512; c += 256) atomicMin(&g_colmin[c], s_cm[c]);
}

// ---------------- final reduce ----------------
__global__ void swav_fin(float* __restrict__ out) {
    __shared__ float red[256];
    int tid = threadIdx.x;
    float s = sqrtf(__uint_as_float(g_colmin[tid])) +
              sqrtf(__uint_as_float(g_colmin[tid + 256]));
    red[tid] = s;
    __syncthreads();
    for (int o = 128; o; o >>= 1) {
        if (tid < o) red[tid] += red[tid + o];
        __syncthreads();
    }
    if (tid == 0) {
        float rs = 0.f;
        for (int i = 0; i < GRID; i++) rs += g_partial[i];
        out[O_PROT] = 0.5f * (rs / (float)NROWS) + 0.5f * (red[0] / 512.f);
    }
}

extern "C" void kernel_launch(void* const* d_in, const int* in_sizes, int n_in,
                              void* d_out, int out_size) {
    const float* x   = (const float*)d_in[0];
    const float* W   = (const float*)d_in[1];
    const float* rec = (const float*)d_in[2];
    const float* kl  = (const float*)d_in[3];
    const float* mmd = (const float*)d_in[4];
    float* out = (float*)d_out;
    cudaFuncSetAttribute(swav_main, cudaFuncAttributeMaxDynamicSharedMemorySize, SMEM_BYTES);
    swav_prep<<<512, 32>>>(W, rec, kl, mmd, out);
    swav_main<<<GRID, 256, SMEM_BYTES>>>(x, out);
    swav_fin<<<1, 256>>>(out);
}

// round 10
// speedup vs baseline: 1.0669x; 1.0669x over previous
#include <cuda_runtime.h>
#include <cuda_bf16.h>
#include <cstdint>

#define NROWS   131072
#define NT2     2048          // tiles of 64 rows
#define O_XN2   8388608
#define O_PROTO 16777216
#define O_CVAE  83886080
#define O_PROT  83886081
#define GRID    152
#define INF_F   __int_as_float(0x7f800000)

__device__ float    g_b2[512];
__device__ unsigned g_colmin[512];
__device__ float    g_partial[GRID];

__device__ __forceinline__ void mma16816(float* c, const uint32_t* a, uint32_t b0, uint32_t b1) {
    asm volatile(
        "mma.sync.aligned.m16n8k16.row.col.f32.bf16.bf16.f32 "
        "{%0,%1,%2,%3}, {%4,%5,%6,%7}, {%8,%9}, {%0,%1,%2,%3};"
        : "+f"(c[0]), "+f"(c[1]), "+f"(c[2]), "+f"(c[3])
        : "r"(a[0]), "r"(a[1]), "r"(a[2]), "r"(a[3]), "r"(b0), "r"(b1));
}

__device__ __forceinline__ void ldsm_x4(uint32_t* r, uint32_t addr) {
    asm volatile("ldmatrix.sync.aligned.m8n8.x4.shared.b16 {%0,%1,%2,%3}, [%4];"
        : "=r"(r[0]), "=r"(r[1]), "=r"(r[2]), "=r"(r[3]) : "r"(addr));
}

__device__ __forceinline__ uint32_t smem_u32(const void* p) {
    uint32_t a;
    asm("{ .reg .u64 t; cvta.to.shared.u64 t, %1; cvt.u32.u64 %0, t; }" : "=r"(a) : "l"(p));
    return a;
}

__device__ __forceinline__ void split2(float x, float y, uint32_t& hi, uint32_t& lo) {
    unsigned short hx = __bfloat16_as_ushort(__float2bfloat16(x));
    unsigned short hy = __bfloat16_as_ushort(__float2bfloat16(y));
    float rx = x - __bfloat162float(__ushort_as_bfloat16(hx));
    float ry = y - __bfloat162float(__ushort_as_bfloat16(hy));
    unsigned short lx = __bfloat16_as_ushort(__float2bfloat16(rx));
    unsigned short ly = __bfloat16_as_ushort(__float2bfloat16(ry));
    hi = (uint32_t)hx | ((uint32_t)hy << 16);
    lo = (uint32_t)lx | ((uint32_t)ly << 16);
}

// ---------------- prep: b2, colmin reset, cvae ----------------
__global__ void swav_prep(const float* __restrict__ W, const float* __restrict__ rec,
                          const float* __restrict__ kl, const float* __restrict__ mmd,
                          float* __restrict__ out) {
    int wid = threadIdx.x >> 5, lane = threadIdx.x & 31;
    int k = blockIdx.x * 8 + wid;                    // grid 64 x 256
    float2 v = ((const float2*)(W + k * 64))[lane];
    float s = v.x * v.x + v.y * v.y;
    #pragma unroll
    for (int m = 16; m; m >>= 1) s += __shfl_xor_sync(0xffffffffu, s, m);
    if (lane == 0) { g_b2[k] = s; g_colmin[k] = 0x7f800000u; }
    if (blockIdx.x == 0 && threadIdx.x == 0)
        out[O_CVAE] = rec[0] + 0.5f * kl[0] + mmd[0];
}

// ---------------- main ----------------
__global__ void __launch_bounds__(256, 1)
swav_main(const float* __restrict__ x, const float* __restrict__ W, float* __restrict__ out) {
    __shared__ uint32_t sAhi[64 * 36];   // 64 rows x 64 bf16 (32 u32) pad to 36
    __shared__ uint32_t sAlo[64 * 36];
    __shared__ float    sRow[64 * 9];    // per-row per-warp partial min (pad 9)
    __shared__ float    sRed[64];

    int tid = threadIdx.x, wid = tid >> 5, lane = tid & 31;
    int g = lane >> 2, t = lane & 3;
    int wbase = wid * 64;                // warp owns cols [wbase, wbase+64)

    // ---- B fragments: load W once, split bf16 hi/lo, keep in registers ----
    uint32_t Bh[8][4][2], Bl[8][4][2];
    float b2p1[8][2], cm[8][2];
    #pragma unroll
    for (int nt = 0; nt < 8; nt++) {
        int col = wbase + nt * 8 + g;
        #pragma unroll
        for (int ks = 0; ks < 4; ks++) {
            const float2* p = (const float2*)(W + col * 64 + ks * 16) + t;
            float2 v0 = p[0];   // k = 16ks+2t, +1
            float2 v1 = p[4];   // k = 16ks+8+2t, +1
            split2(v0.x, v0.y, Bh[nt][ks][0], Bl[nt][ks][0]);
            split2(v1.x, v1.y, Bh[nt][ks][1], Bl[nt][ks][1]);
        }
        int c0 = wbase + nt * 8 + 2 * t;
        b2p1[nt][0] = 1.0f + g_b2[c0];
        b2p1[nt][1] = 1.0f + g_b2[c0 + 1];
        cm[nt][0] = INF_F; cm[nt][1] = INF_F;
    }

    uint32_t aHiBase = smem_u32(sAhi);
    uint32_t aLoBase = smem_u32(sAlo);
    // ldmatrix lane address components (row within tile-group, k-half)
    int lm_row = lane & 15;
    uint32_t lm_koff = (lane & 16) ? 16u : 0u;

    float rowacc = 0.f;

    for (int tile = blockIdx.x; tile < NT2; tile += GRID) {
        int rb = tile * 64;

        // ---- normalize own 8 rows, write xn x2, stage split bf16 in smem ----
        #pragma unroll
        for (int r = 0; r < 8; r++) {
            int row = rb + wid * 8 + r;
            float2 v = ((const float2*)x)[row * 32 + lane];
            float s = v.x * v.x + v.y * v.y;
            #pragma unroll
            for (int m = 16; m; m >>= 1) s += __shfl_xor_sync(0xffffffffu, s, m);
            float inv = 1.0f / fmaxf(sqrtf(s), 1e-12f);
            float2 xnv = make_float2(v.x * inv, v.y * inv);
            ((float2*)out)[row * 32 + lane] = xnv;
            ((float2*)(out + O_XN2))[row * 32 + lane] = xnv;
            uint32_t hi, lo;
            split2(xnv.x, xnv.y, hi, lo);
            sAhi[(wid * 8 + r) * 36 + lane] = hi;
            sAlo[(wid * 8 + r) * 36 + lane] = lo;
        }
        __syncthreads();

        // ---- 4 rowgroups of 16 rows: A via ldmatrix, B from registers ----
        for (int rg = 0; rg < 4; rg++) {
            uint32_t Ah[4][4], Al[4][4];
            uint32_t rowoff = (uint32_t)(rg * 16 + lm_row) * 144u + lm_koff;
            #pragma unroll
            for (int ks = 0; ks < 4; ks++) {
                ldsm_x4(Ah[ks], aHiBase + rowoff + ks * 32u);
                ldsm_x4(Al[ks], aLoBase + rowoff + ks * 32u);
            }

            float C[8][4];
            #pragma unroll
            for (int nt = 0; nt < 8; nt++)
                C[nt][0] = C[nt][1] = C[nt][2] = C[nt][3] = 0.f;

            #pragma unroll
            for (int ks = 0; ks < 4; ks++) {
                #pragma unroll
                for (int nt = 0; nt < 8; nt++) {
                    mma16816(C[nt], Ah[ks], Bh[nt][ks][0], Bh[nt][ks][1]);
                    mma16816(C[nt], Al[ks], Bh[nt][ks][0], Bh[nt][ks][1]);
                    mma16816(C[nt], Ah[ks], Bl[nt][ks][0], Bl[nt][ks][1]);
                }
            }

            // ---- epilogue: proto stores + squared-distance mins ----
            int r0 = rb + rg * 16 + g, r1 = r0 + 8;
            float rm0 = INF_F, rm1 = INF_F;
            #pragma unroll
            for (int nt = 0; nt < 8; nt++) {
                int c0 = wbase + nt * 8 + 2 * t;
                ((float2*)(out + O_PROTO))[(r0 * 512 + c0) >> 1] = make_float2(C[nt][0], C[nt][1]);
                ((float2*)(out + O_PROTO))[(r1 * 512 + c0) >> 1] = make_float2(C[nt][2], C[nt][3]);
                float u00 = fmaxf(fmaf(-2.f, C[nt][0], b2p1[nt][0]), 1e-12f);
                float u01 = fmaxf(fmaf(-2.f, C[nt][1], b2p1[nt][1]), 1e-12f);
                float u10 = fmaxf(fmaf(-2.f, C[nt][2], b2p1[nt][0]), 1e-12f);
                float u11 = fmaxf(fmaf(-2.f, C[nt][3], b2p1[nt][1]), 1e-12f);
                rm0 = fminf(rm0, fminf(u00, u01));
                rm1 = fminf(rm1, fminf(u10, u11));
                cm[nt][0] = fminf(cm[nt][0], fminf(u00, u10));
                cm[nt][1] = fminf(cm[nt][1], fminf(u01, u11));
            }
            rm0 = fminf(rm0, __shfl_xor_sync(0xffffffffu, rm0, 1));
            rm0 = fminf(rm0, __shfl_xor_sync(0xffffffffu, rm0, 2));
            rm1 = fminf(rm1, __shfl_xor_sync(0xffffffffu, rm1, 1));
            rm1 = fminf(rm1, __shfl_xor_sync(0xffffffffu, rm1, 2));
            if (t == 0) {
                sRow[(rg * 16 + g) * 9 + wid] = rm0;
                sRow[(rg * 16 + 8 + g) * 9 + wid] = rm1;
            }
        }
        __syncthreads();

        // ---- combine row-mins across warps, accumulate sqrt ----
        if (tid < 64) {
            float m = sRow[tid * 9];
            #pragma unroll
            for (int w = 1; w < 8; w++) m = fminf(m, sRow[tid * 9 + w]);
            rowacc += sqrtf(m);
        }
    }

    // ---- col-min: reduce over g lanes, one global atomicMin ----
    #pragma unroll
    for (int nt = 0; nt < 8; nt++) {
        float v0 = cm[nt][0], v1 = cm[nt][1];
        #pragma unroll
        for (int m = 4; m <= 16; m <<= 1) {
            v0 = fminf(v0, __shfl_xor_sync(0xffffffffu, v0, m));
            v1 = fminf(v1, __shfl_xor_sync(0xffffffffu, v1, m));
        }
        if (g == 0) {
            int c0 = wbase + nt * 8 + 2 * t;
            atomicMin(&g_colmin[c0], __float_as_uint(v0));
            atomicMin(&g_colmin[c0 + 1], __float_as_uint(v1));
        }
    }

    // ---- block row-sum partial ----
    if (tid < 64) sRed[tid] = rowacc;
    __syncthreads();
    if (tid == 0) {
        float s = 0.f;
        for (int i = 0; i < 64; i++) s += sRed[i];
        g_partial[blockIdx.x] = s;
    }
}

// ---------------- final reduce ----------------
__global__ void swav_fin(float* __restrict__ out) {
    __shared__ float red[256];
    int tid = threadIdx.x;
    float s = sqrtf(__uint_as_float(g_colmin[tid])) +
              sqrtf(__uint_as_float(g_colmin[tid + 256]));
    red[tid] = s;
    __syncthreads();
    for (int o = 128; o; o >>= 1) {
        if (tid < o) red[tid] += red[tid + o];
        __syncthreads();
    }
    if (tid == 0) {
        float rs = 0.f;
        for (int i = 0; i < GRID; i++) rs += g_partial[i];
        out[O_PROT] = 0.5f * (rs / (float)NROWS) + 0.5f * (red[0] / 512.f);
    }
}

extern "C" void kernel_launch(void* const* d_in, const int* in_sizes, int n_in,
                              void* d_out, int out_size) {
    const float* x   = (const float*)d_in[0];
    const float* W   = (const float*)d_in[1];
    const float* rec = (const float*)d_in[2];
    const float* kl  = (const float*)d_in[3];
    const float* mmd = (const float*)d_in[4];
    float* out = (float*)d_out;
    swav_prep<<<64, 256>>>(W, rec, kl, mmd, out);
    swav_main<<<GRID, 256>>>(x, W, out);
    swav_fin<<<1, 256>>>(out);
}

// round 15
// speedup vs baseline: 1.6950x; 1.5888x over previous
#include <cuda_runtime.h>
#include <cuda_fp16.h>
#include <cstdint>

#define NROWS   131072
#define NT      2048          // tiles of 64 rows
#define O_XN2   8388608
#define O_PROTO 16777216
#define O_CVAE  83886080
#define O_PROT  83886081
#define GRID    152
#define INF_F   __int_as_float(0x7f800000)

__device__ unsigned g_counter = 0;
__device__ float    g_partial[GRID];
__device__ unsigned g_cmb[GRID * 512];

__device__ __forceinline__ void mma16816(float* c, const uint32_t* a, uint32_t b0, uint32_t b1) {
    asm volatile(
        "mma.sync.aligned.m16n8k16.row.col.f32.f16.f16.f32 "
        "{%0,%1,%2,%3}, {%4,%5,%6,%7}, {%8,%9}, {%0,%1,%2,%3};"
        : "+f"(c[0]), "+f"(c[1]), "+f"(c[2]), "+f"(c[3])
        : "r"(a[0]), "r"(a[1]), "r"(a[2]), "r"(a[3]), "r"(b0), "r"(b1));
}
__device__ __forceinline__ void ldsm_x4(uint32_t* r, uint32_t addr) {
    asm volatile("ldmatrix.sync.aligned.m8n8.x4.shared.b16 {%0,%1,%2,%3}, [%4];"
        : "=r"(r[0]), "=r"(r[1]), "=r"(r[2]), "=r"(r[3]) : "r"(addr));
}
__device__ __forceinline__ uint32_t smem_u32(const void* p) {
    uint32_t a;
    asm("{ .reg .u64 t; cvta.to.shared.u64 t, %1; cvt.u32.u64 %0, t; }" : "=r"(a) : "l"(p));
    return a;
}
__device__ __forceinline__ uint32_t packh2(float x, float y) {
    __half2 h = __floats2half2_rn(x, y);          // x -> lo, y -> hi
    return *reinterpret_cast<uint32_t*>(&h);
}

__global__ void __launch_bounds__(512, 1)
swav_all(const float* __restrict__ x, const float* __restrict__ W,
         const float* __restrict__ rec, const float* __restrict__ kl,
         const float* __restrict__ mmd, float* __restrict__ out) {
    __shared__ __align__(16) unsigned char sA[64 * 144];   // 64 rows x 72 fp16 (pad)
    __shared__ float sB2[512];
    __shared__ float sRow[64 * 17];
    __shared__ float sRed[64];
    __shared__ unsigned sFlag;

    int tid = threadIdx.x, wid = tid >> 5, lane = tid & 31;
    int g = lane >> 2, t = lane & 3;
    int wbase = wid * 32;                 // warp owns cols [wbase, wbase+32)
    int bid = blockIdx.x;

    // ---- B fragments: W -> fp16, registers (once) ----
    uint32_t Bf[4][4][2];
    #pragma unroll
    for (int nt = 0; nt < 4; nt++) {
        int col = wbase + nt * 8 + g;
        #pragma unroll
        for (int ks = 0; ks < 4; ks++) {
            const float2* p = (const float2*)(W + col * 64 + ks * 16) + t;
            float2 v0 = p[0], v1 = p[4];
            Bf[nt][ks][0] = packh2(v0.x, v0.y);
            Bf[nt][ks][1] = packh2(v1.x, v1.y);
        }
    }
    // ---- 1 + ||W_k||^2 ----
    {
        const float4* p = (const float4*)(W + tid * 64);
        float s = 0.f;
        #pragma unroll
        for (int i = 0; i < 16; i++) {
            float4 v = p[i];
            s += v.x * v.x + v.y * v.y + v.z * v.z + v.w * v.w;
        }
        sB2[tid] = 1.0f + s;
    }
    __syncthreads();
    float b2[4][2];
    float cmv[4][2];
    #pragma unroll
    for (int nt = 0; nt < 4; nt++) {
        int c0 = wbase + nt * 8 + 2 * t;
        b2[nt][0] = sB2[c0]; b2[nt][1] = sB2[c0 + 1];
        cmv[nt][0] = INF_F;  cmv[nt][1] = INF_F;
    }

    uint32_t aBase = smem_u32(sA);
    uint32_t aLane = (uint32_t)(lane & 15) * 144u + ((lane & 16) ? 16u : 0u);
    float rowacc = 0.f;

    for (int tile = bid; tile < NT; tile += GRID) {
        int rb = tile * 64;

        // ---- normalize 4 rows/warp, write xn x2, stage fp16 A ----
        #pragma unroll
        for (int r = 0; r < 4; r++) {
            int rl = wid * 4 + r;
            int row = rb + rl;
            float2 v = ((const float2*)x)[row * 32 + lane];
            float s = v.x * v.x + v.y * v.y;
            #pragma unroll
            for (int m = 16; m; m >>= 1) s += __shfl_xor_sync(0xffffffffu, s, m);
            float inv = 1.0f / fmaxf(sqrtf(s), 1e-12f);
            float2 xnv = make_float2(v.x * inv, v.y * inv);
            ((float2*)out)[row * 32 + lane] = xnv;
            ((float2*)(out + O_XN2))[row * 32 + lane] = xnv;
            *(uint32_t*)(sA + rl * 144 + lane * 4) = packh2(xnv.x, xnv.y);
        }
        __syncthreads();

        // ---- 4 rowgroups of 16 rows ----
        for (int rg = 0; rg < 4; rg++) {
            uint32_t Af[4][4];
            uint32_t ra = aBase + (uint32_t)rg * (16u * 144u) + aLane;
            #pragma unroll
            for (int ks = 0; ks < 4; ks++) ldsm_x4(Af[ks], ra + ks * 32u);

            float C[4][4];
            #pragma unroll
            for (int nt = 0; nt < 4; nt++)
                C[nt][0] = C[nt][1] = C[nt][2] = C[nt][3] = 0.f;
            #pragma unroll
            for (int ks = 0; ks < 4; ks++)
                #pragma unroll
                for (int nt = 0; nt < 4; nt++)
                    mma16816(C[nt], Af[ks], Bf[nt][ks][0], Bf[nt][ks][1]);

            // ---- epilogue ----
            int r0 = rb + rg * 16 + g, r1 = r0 + 8;
            float rm0 = INF_F, rm1 = INF_F;
            #pragma unroll
            for (int nt = 0; nt < 4; nt++) {
                int c0 = wbase + nt * 8 + 2 * t;
                ((float2*)(out + O_PROTO))[((size_t)r0 * 512 + c0) >> 1] = make_float2(C[nt][0], C[nt][1]);
                ((float2*)(out + O_PROTO))[((size_t)r1 * 512 + c0) >> 1] = make_float2(C[nt][2], C[nt][3]);
                float u00 = fmaxf(fmaf(-2.f, C[nt][0], b2[nt][0]), 1e-12f);
                float u01 = fmaxf(fmaf(-2.f, C[nt][1], b2[nt][1]), 1e-12f);
                float u10 = fmaxf(fmaf(-2.f, C[nt][2], b2[nt][0]), 1e-12f);
                float u11 = fmaxf(fmaf(-2.f, C[nt][3], b2[nt][1]), 1e-12f);
                rm0 = fminf(rm0, fminf(u00, u01));
                rm1 = fminf(rm1, fminf(u10, u11));
                cmv[nt][0] = fminf(cmv[nt][0], fminf(u00, u10));
                cmv[nt][1] = fminf(cmv[nt][1], fminf(u01, u11));
            }
            rm0 = fminf(rm0, __shfl_xor_sync(0xffffffffu, rm0, 1));
            rm0 = fminf(rm0, __shfl_xor_sync(0xffffffffu, rm0, 2));
            rm1 = fminf(rm1, __shfl_xor_sync(0xffffffffu, rm1, 1));
            rm1 = fminf(rm1, __shfl_xor_sync(0xffffffffu, rm1, 2));
            if (t == 0) {
                sRow[(rg * 16 + g) * 17 + wid] = rm0;
                sRow[(rg * 16 + 8 + g) * 17 + wid] = rm1;
            }
        }
        __syncthreads();
        if (tid < 64) {
            float m = sRow[tid * 17];
            #pragma unroll
            for (int w = 1; w < 16; w++) m = fminf(m, sRow[tid * 17 + w]);
            rowacc += sqrtf(m);
        }
    }

    // ---- per-block col-min + row-sum partials ----
    #pragma unroll
    for (int nt = 0; nt < 4; nt++) {
        #pragma unroll
        for (int jj = 0; jj < 2; jj++) {
            float v = cmv[nt][jj];
            v = fminf(v, __shfl_xor_sync(0xffffffffu, v, 4));
            v = fminf(v, __shfl_xor_sync(0xffffffffu, v, 8));
            v = fminf(v, __shfl_xor_sync(0xffffffffu, v, 16));
            if (g == 0)
                g_cmb[bid * 512 + wbase + nt * 8 + 2 * t + jj] = __float_as_uint(v);
        }
    }
    if (tid < 64) sRed[tid] = rowacc;
    __syncthreads();
    if (tid == 0) {
        float s = 0.f;
        for (int i = 0; i < 64; i++) s += sRed[i];
        g_partial[bid] = s;
    }
    __threadfence();
    if (tid == 0) {
        unsigned old = atomicAdd(&g_counter, 1);
        sFlag = (old == (unsigned)(gridDim.x - 1)) ? 1u : 0u;
    }
    __syncthreads();

    // ---- last block: finalize scalars ----
    if (sFlag) {
        __threadfence();
        float m = INF_F;
        for (int b = 0; b < GRID; b++)
            m = fminf(m, __uint_as_float(g_cmb[b * 512 + tid]));
        sB2[tid] = sqrtf(m);
        __syncthreads();
        for (int o = 256; o; o >>= 1) {
            if (tid < o) sB2[tid] += sB2[tid + o];
            __syncthreads();
        }
        if (tid == 0) {
            float rs = 0.f;
            for (int i = 0; i < GRID; i++) rs += g_partial[i];
            out[O_PROT] = 0.5f * (rs / (float)NROWS) + 0.5f * (sB2[0] / 512.f);
            out[O_CVAE] = rec[0] + 0.5f * kl[0] + mmd[0];
            g_counter = 0;
        }
    }
}

extern "C" void kernel_launch(void* const* d_in, const int* in_sizes, int n_in,
                              void* d_out, int out_size) {
    const float* x   = (const float*)d_in[0];
    const float* W   = (const float*)d_in[1];
    const float* rec = (const float*)d_in[2];
    const float* kl  = (const float*)d_in[3];
    const float* mmd = (const float*)d_in[4];
    float* out = (float*)d_out;
    swav_all<<<GRID, 512>>>(x, W, rec, kl, mmd, out);
}

// round 16
// speedup vs baseline: 2.4969x; 1.4731x over previous
#include <cuda_runtime.h>
#include <cuda_fp16.h>
#include <cstdint>

#define NROWS   131072
#define NT      1024          // tiles of 128 rows
#define O_XN2   8388608
#define O_PROTO 16777216
#define O_CVAE  83886080
#define O_PROT  83886081
#define GRID    152
#define INF_F   __int_as_float(0x7f800000)

// dynamic smem layout (bytes)
#define OFF_X0   0            // 128 rows x 64 f32 = 32768
#define OFF_X1   32768
#define OFF_A    65536        // 128 x 144 B fp16 staged (pad 72 halves)
#define OFF_ROW  84224        // 128*17 f32
#define OFF_RED  92928        // 128 f32
#define OFF_B2   93440        // 512 f32
#define OFF_FLAG 95488
#define SMEM_SZ  95744

__device__ unsigned g_counter = 0;
__device__ float    g_partial[GRID];
__device__ unsigned g_cmb[GRID * 512];

__device__ __forceinline__ void mma16816(float* c, const uint32_t* a, uint32_t b0, uint32_t b1) {
    asm volatile(
        "mma.sync.aligned.m16n8k16.row.col.f32.f16.f16.f32 "
        "{%0,%1,%2,%3}, {%4,%5,%6,%7}, {%8,%9}, {%0,%1,%2,%3};"
        : "+f"(c[0]), "+f"(c[1]), "+f"(c[2]), "+f"(c[3])
        : "r"(a[0]), "r"(a[1]), "r"(a[2]), "r"(a[3]), "r"(b0), "r"(b1));
}
__device__ __forceinline__ void ldsm_x4(uint32_t* r, uint32_t addr) {
    asm volatile("ldmatrix.sync.aligned.m8n8.x4.shared.b16 {%0,%1,%2,%3}, [%4];"
        : "=r"(r[0]), "=r"(r[1]), "=r"(r[2]), "=r"(r[3]) : "r"(addr));
}
__device__ __forceinline__ uint32_t smem_u32(const void* p) {
    uint32_t a;
    asm("{ .reg .u64 t; cvta.to.shared.u64 t, %1; cvt.u32.u64 %0, t; }" : "=r"(a) : "l"(p));
    return a;
}
__device__ __forceinline__ uint32_t packh2(float x, float y) {
    __half2 h = __floats2half2_rn(x, y);
    return *reinterpret_cast<uint32_t*>(&h);
}
__device__ __forceinline__ void cp16(uint32_t saddr, const void* gptr) {
    asm volatile("cp.async.ca.shared.global [%0], [%1], 16;" :: "r"(saddr), "l"(gptr) : "memory");
}
#define CP_COMMIT() asm volatile("cp.async.commit_group;" ::: "memory")
#define CP_WAIT0()  asm volatile("cp.async.wait_group 0;" ::: "memory")

__global__ void __launch_bounds__(512, 1)
swav_all(const float* __restrict__ x, const float* __restrict__ W,
         const float* __restrict__ rec, const float* __restrict__ kl,
         const float* __restrict__ mmd, float* __restrict__ out) {
    extern __shared__ __align__(16) unsigned char smem[];
    uint32_t sb = smem_u32(smem);
    float* sRow = (float*)(smem + OFF_ROW);
    float* sRed = (float*)(smem + OFF_RED);
    float* sB2  = (float*)(smem + OFF_B2);
    unsigned* sFlag = (unsigned*)(smem + OFF_FLAG);

    int tid = threadIdx.x, wid = tid >> 5, lane = tid & 31;
    int g = lane >> 2, t = lane & 3;
    int wbase = wid * 32;
    int bid = blockIdx.x;

    // ---- initial prefetch: tile = bid into buffer 0 (4 x 16B per thread) ----
    {
        const char* gp = (const char*)(x + (size_t)bid * 128 * 64);
        #pragma unroll
        for (int q = 0; q < 4; q++)
            cp16(sb + OFF_X0 + (tid + q * 512) * 16, gp + (tid + q * 512) * 16);
        CP_COMMIT();
    }

    // ---- B fragments: W -> fp16 registers (overlaps prefetch) ----
    uint32_t Bf[4][4][2];
    #pragma unroll
    for (int nt = 0; nt < 4; nt++) {
        int col = wbase + nt * 8 + g;
        #pragma unroll
        for (int ks = 0; ks < 4; ks++) {
            const float2* p = (const float2*)(W + col * 64 + ks * 16) + t;
            float2 v0 = p[0], v1 = p[4];
            Bf[nt][ks][0] = packh2(v0.x, v0.y);
            Bf[nt][ks][1] = packh2(v1.x, v1.y);
        }
    }
    {   // 1 + ||W_k||^2
        const float4* p = (const float4*)(W + tid * 64);
        float s = 0.f;
        #pragma unroll
        for (int i = 0; i < 16; i++) {
            float4 v = p[i];
            s += v.x * v.x + v.y * v.y + v.z * v.z + v.w * v.w;
        }
        sB2[tid] = 1.0f + s;
    }
    __syncthreads();
    float b2[4][2], cmv[4][2];
    #pragma unroll
    for (int nt = 0; nt < 4; nt++) {
        int c0 = wbase + nt * 8 + 2 * t;
        b2[nt][0] = sB2[c0]; b2[nt][1] = sB2[c0 + 1];
        cmv[nt][0] = INF_F;  cmv[nt][1] = INF_F;
    }

    uint32_t aBase = sb + OFF_A;
    uint32_t aLane = (uint32_t)(lane & 15) * 144u + ((lane & 16) ? 16u : 0u);
    float rowacc = 0.f;
    int pbuf = 0;

    for (int tile = bid; tile < NT; tile += GRID) {
        int rb = tile * 128;
        uint32_t xb = sb + (pbuf ? OFF_X1 : OFF_X0);

        CP_WAIT0();
        __syncthreads();

        // ---- prefetch next tile into other buffer ----
        int ntile = tile + GRID;
        if (ntile < NT) {
            uint32_t xo = sb + (pbuf ? OFF_X0 : OFF_X1);
            const char* gp = (const char*)(x + (size_t)ntile * 128 * 64);
            #pragma unroll
            for (int q = 0; q < 4; q++)
                cp16(xo + (tid + q * 512) * 16, gp + (tid + q * 512) * 16);
        }
        CP_COMMIT();

        // ---- normalize 8 rows/warp from smem, write xn x2, stage fp16 A ----
        #pragma unroll
        for (int r = 0; r < 8; r++) {
            int rl = wid * 8 + r;
            int row = rb + rl;
            float2 v;
            asm volatile("ld.shared.v2.f32 {%0,%1}, [%2];"
                : "=f"(v.x), "=f"(v.y) : "r"(xb + (rl * 32 + lane) * 8));
            float s = v.x * v.x + v.y * v.y;
            #pragma unroll
            for (int m = 16; m; m >>= 1) s += __shfl_xor_sync(0xffffffffu, s, m);
            float inv = 1.0f / fmaxf(sqrtf(s), 1e-12f);
            float2 xnv = make_float2(v.x * inv, v.y * inv);
            ((float2*)out)[row * 32 + lane] = xnv;
            ((float2*)(out + O_XN2))[row * 32 + lane] = xnv;
            asm volatile("st.shared.b32 [%0], %1;"
                :: "r"(aBase + rl * 144u + lane * 4u), "r"(packh2(xnv.x, xnv.y)));
        }
        __syncthreads();

        // ---- 8 rowgroups of 16 rows ----
        #pragma unroll 1
        for (int rg = 0; rg < 8; rg++) {
            uint32_t Af[4][4];
            uint32_t ra = aBase + (uint32_t)rg * (16u * 144u) + aLane;
            #pragma unroll
            for (int ks = 0; ks < 4; ks++) ldsm_x4(Af[ks], ra + ks * 32u);

            float C[4][4];
            #pragma unroll
            for (int nt = 0; nt < 4; nt++)
                C[nt][0] = C[nt][1] = C[nt][2] = C[nt][3] = 0.f;
            #pragma unroll
            for (int ks = 0; ks < 4; ks++)
                #pragma unroll
                for (int nt = 0; nt < 4; nt++)
                    mma16816(C[nt], Af[ks], Bf[nt][ks][0], Bf[nt][ks][1]);

            int r0 = rb + rg * 16 + g, r1 = r0 + 8;
            float rm0 = INF_F, rm1 = INF_F;
            #pragma unroll
            for (int nt = 0; nt < 4; nt++) {
                int c0 = wbase + nt * 8 + 2 * t;
                ((float2*)(out + O_PROTO))[((size_t)r0 * 512 + c0) >> 1] = make_float2(C[nt][0], C[nt][1]);
                ((float2*)(out + O_PROTO))[((size_t)r1 * 512 + c0) >> 1] = make_float2(C[nt][2], C[nt][3]);
                float u00 = fmaxf(fmaf(-2.f, C[nt][0], b2[nt][0]), 1e-12f);
                float u01 = fmaxf(fmaf(-2.f, C[nt][1], b2[nt][1]), 1e-12f);
                float u10 = fmaxf(fmaf(-2.f, C[nt][2], b2[nt][0]), 1e-12f);
                float u11 = fmaxf(fmaf(-2.f, C[nt][3], b2[nt][1]), 1e-12f);
                rm0 = fminf(rm0, fminf(u00, u01));
                rm1 = fminf(rm1, fminf(u10, u11));
                cmv[nt][0] = fminf(cmv[nt][0], fminf(u00, u10));
                cmv[nt][1] = fminf(cmv[nt][1], fminf(u01, u11));
            }
            rm0 = fminf(rm0, __shfl_xor_sync(0xffffffffu, rm0, 1));
            rm0 = fminf(rm0, __shfl_xor_sync(0xffffffffu, rm0, 2));
            rm1 = fminf(rm1, __shfl_xor_sync(0xffffffffu, rm1, 1));
            rm1 = fminf(rm1, __shfl_xor_sync(0xffffffffu, rm1, 2));
            if (t == 0) {
                sRow[(rg * 16 + g) * 17 + wid] = rm0;
                sRow[(rg * 16 + 8 + g) * 17 + wid] = rm1;
            }
        }
        __syncthreads();
        if (tid < 128) {
            float m = sRow[tid * 17];
            #pragma unroll
            for (int w = 1; w < 16; w++) m = fminf(m, sRow[tid * 17 + w]);
            rowacc += sqrtf(m);
        }
        pbuf ^= 1;
    }

    // ---- per-block partials ----
    #pragma unroll
    for (int nt = 0; nt < 4; nt++) {
        #pragma unroll
        for (int jj = 0; jj < 2; jj++) {
            float v = cmv[nt][jj];
            v = fminf(v, __shfl_xor_sync(0xffffffffu, v, 4));
            v = fminf(v, __shfl_xor_sync(0xffffffffu, v, 8));
            v = fminf(v, __shfl_xor_sync(0xffffffffu, v, 16));
            if (g == 0)
                g_cmb[bid * 512 + wbase + nt * 8 + 2 * t + jj] = __float_as_uint(v);
        }
    }
    if (tid < 128) sRed[tid] = rowacc;
    __syncthreads();
    if (tid == 0) {
        float s = 0.f;
        for (int i = 0; i < 128; i++) s += sRed[i];
        g_partial[bid] = s;
    }
    __threadfence();
    if (tid == 0) {
        unsigned old = atomicAdd(&g_counter, 1);
        *sFlag = (old == (unsigned)(gridDim.x - 1)) ? 1u : 0u;
    }
    __syncthreads();

    // ---- last block: finalize scalars ----
    if (*sFlag) {
        __threadfence();
        float m = INF_F;
        for (int b = 0; b < GRID; b++)
            m = fminf(m, __uint_as_float(g_cmb[b * 512 + tid]));
        sB2[tid] = sqrtf(m);
        __syncthreads();
        for (int o = 256; o; o >>= 1) {
            if (tid < o) sB2[tid] += sB2[tid + o];
            __syncthreads();
        }
        if (tid == 0) {
            float rs = 0.f;
            for (int i = 0; i < GRID; i++) rs += g_partial[i];
            out[O_PROT] = 0.5f * (rs / (float)NROWS) + 0.5f * (sB2[0] / 512.f);
            out[O_CVAE] = rec[0] + 0.5f * kl[0] + mmd[0];
            g_counter = 0;
        }
    }
}

extern "C" void kernel_launch(void* const* d_in, const int* in_sizes, int n_in,
                              void* d_out, int out_size) {
    const float* x   = (const float*)d_in[0];
    const float* W   = (const float*)d_in[1];
    const float* rec = (const float*)d_in[2];
    const float* kl  = (const float*)d_in[3];
    const float* mmd = (const float*)d_in[4];
    float* out = (float*)d_out;
    cudaFuncSetAttribute(swav_all, cudaFuncAttributeMaxDynamicSharedMemorySize, SMEM_SZ);
    swav_all<<<GRID, 512, SMEM_SZ>>>(x, W, rec, kl, mmd, out);
}